// round 7
// baseline (speedup 1.0000x reference)
#include <cuda_runtime.h>
#include <cuda_bf16.h>
#include <cstdint>

// ---------------- problem constants ----------------
#define NW   2048
#define TC   12
#define TS   4
#define CD   64
#define SD   64
#define WD   256
#define HH   128
#define Hd   256      // H
#define G    512      // 4*HH
#define XW   768      // WD + 2*H
#define NPOS 47
#define NNER 13

// ---------------- scratch (device globals; no allocs allowed) ----------------
__device__ float g_x_char[NW * TC * CD];
__device__ float g_x_syl[NW * TS * SD];
__device__ float g_gin_char[2 * NW * TC * G];
__device__ float g_gin_syl[2 * NW * TS * G];
__device__ float g_gin_word[2 * NW * G];
__device__ float g_out_char[TC * NW * Hd];
__device__ float g_out_syl[TS * NW * Hd];
__device__ float g_h[2 * NW * HH];
__device__ float g_c[2 * NW * HH];
__device__ float g_h0[2 * NW * HH];
__device__ float g_gates[2 * NW * G];
__device__ float g_logits_char[TC * NW];
__device__ float g_logits_syl[TS * NW];
__device__ float g_xword[NW * XW];
__device__ float g_outword[NW * Hd];

// ---------------- math helpers ----------------
__device__ __forceinline__ float sigf(float x) { return 1.0f / (1.0f + __expf(-x)); }
__device__ __forceinline__ float tanhfast(float x) {
    float t = __expf(-2.0f * fabsf(x));
    float r = (1.0f - t) / (1.0f + t);
    return copysignf(r, x);
}
__device__ __forceinline__ uint32_t smem_u32(const void* p) {
    uint32_t a;
    asm("{ .reg .u64 t; cvta.to.shared.u64 t, %1; cvt.u32.u64 %0, t; }" : "=r"(a) : "l"(p));
    return a;
}
__device__ __forceinline__ void fma2(unsigned long long& d, unsigned long long a, unsigned long long b) {
    asm("fma.rn.f32x2 %0, %1, %2, %0;" : "+l"(d) : "l"(a), "l"(b));
}
__device__ __forceinline__ float upsum(unsigned long long a) {
    return __uint_as_float((uint32_t)a) + __uint_as_float((uint32_t)(a >> 32));
}

// ---------------- gather: embeddings + h0 init ----------------
__global__ void gather_kernel(const int* __restrict__ word_seq, const int* __restrict__ syl_seq,
                              const int* __restrict__ char_seq, const int* __restrict__ feat_seq,
                              const float* __restrict__ emb_char, const float* __restrict__ emb_syl,
                              const float* __restrict__ emb_word, const float* __restrict__ emb_prefix) {
    int idx = blockIdx.x * blockDim.x + threadIdx.x;
    const int n0 = NW * TC * CD;
    const int n1 = n0 + NW * TS * SD;
    const int n2 = n1 + 2 * NW * HH;
    const int n3 = n2 + NW * WD;
    if (idx < n0) {
        int d = idx % CD; int rest = idx / CD; int t = rest % TC; int w = rest / TC;
        g_x_char[idx] = emb_char[char_seq[w * TC + t] * CD + d];
    } else if (idx < n1) {
        int i = idx - n0;
        int d = i % SD; int rest = i / SD; int t = rest % TS; int w = rest / TS;
        g_x_syl[i] = emb_syl[syl_seq[w * TS + t] * SD + d];
    } else if (idx < n2) {
        int i = idx - n1;             // [dir][w][j]
        int j = i % HH; int rest = i / HH; int w = rest % NW; int dir = rest / NW;
        float v = emb_prefix[feat_seq[w] * Hd + dir * HH + j];
        g_h0[i] = v; g_h[i] = v; g_c[i] = 0.0f;
    } else if (idx < n3) {
        int i = idx - n2;
        int d = i % WD; int w = i / WD;
        g_xword[w * XW + d] = emb_word[word_seq[w] * WD + d];
    }
}

__global__ void clear_logits_kernel() {
    int idx = blockIdx.x * blockDim.x + threadIdx.x;
    if (idx < TC * NW) g_logits_char[idx] = 0.0f;
    if (idx < TS * NW) g_logits_syl[idx] = 0.0f;
}

__global__ void reinit_state_kernel() {
    int idx = blockIdx.x * blockDim.x + threadIdx.x;
    if (idx < 2 * NW * HH) { g_h[idx] = g_h0[idx]; g_c[idx] = 0.0f; }
}

// ---------------- generic tiled GEMM:  C = A[M,K] @ B[N,K]^T (+Add)(+b1+b2) ----------------
#define BMt 64
#define BNt 64
#define BKt 16

__global__ void __launch_bounds__(256) gemm64(
    const float* __restrict__ A, long long sAz,
    const float* __restrict__ B, long long sBz,
    const float* __restrict__ Add, long long sAddz, int ldAdd,
    const float* __restrict__ b1, const float* __restrict__ b2, long long sbz,
    float* __restrict__ C, long long sCz,
    int M, int N, int K) {
    __shared__ float As[BKt][BMt];
    __shared__ float Bs[BKt][BNt];
    long long z = blockIdx.z;
    A += z * sAz; B += z * sBz; C += z * sCz;
    if (Add) Add += z * sAddz;
    if (b1) b1 += z * sbz;
    if (b2) b2 += z * sbz;

    int tid = threadIdx.x;
    int bm = blockIdx.y * BMt, bn = blockIdx.x * BNt;
    int ar = tid >> 2, ak = (tid & 3) << 2;
    int ty = tid >> 4, tx = tid & 15;
    float acc[4][4] = {};

    for (int k0 = 0; k0 < K; k0 += BKt) {
        float4 av = *(const float4*)(A + (size_t)(bm + ar) * K + k0 + ak);
        float4 bv = *(const float4*)(B + (size_t)(bn + ar) * K + k0 + ak);
        As[ak + 0][ar] = av.x; As[ak + 1][ar] = av.y; As[ak + 2][ar] = av.z; As[ak + 3][ar] = av.w;
        Bs[ak + 0][ar] = bv.x; Bs[ak + 1][ar] = bv.y; Bs[ak + 2][ar] = bv.z; Bs[ak + 3][ar] = bv.w;
        __syncthreads();
#pragma unroll
        for (int kk = 0; kk < BKt; kk++) {
            float4 a = *(const float4*)&As[kk][ty << 2];
            float4 b = *(const float4*)&Bs[kk][tx << 2];
            float ar4[4] = {a.x, a.y, a.z, a.w};
            float br4[4] = {b.x, b.y, b.z, b.w};
#pragma unroll
            for (int i = 0; i < 4; i++)
#pragma unroll
                for (int j = 0; j < 4; j++)
                    acc[i][j] = fmaf(ar4[i], br4[j], acc[i][j]);
        }
        __syncthreads();
    }
#pragma unroll
    for (int i = 0; i < 4; i++) {
        int m = bm + (ty << 2) + i;
#pragma unroll
        for (int j = 0; j < 4; j++) {
            int n = bn + (tx << 2) + j;
            float v = acc[i][j];
            if (b1) v += b1[n];
            if (b2) v += b2[n];
            if (Add) v += Add[(size_t)m * ldAdd + n];
            C[(size_t)m * N + n] = v;
        }
    }
}

// ---------------- attention GEMM: logits[m] += sum_n tanh(A@B^T + ba)[m,n]*wv[n] ----------------
__global__ void __launch_bounds__(256) gemm_attn(
    const float* __restrict__ A, const float* __restrict__ B,
    const float* __restrict__ ba, const float* __restrict__ wv,
    float* __restrict__ logits, int M, int K) {
    __shared__ float As[BKt][BMt];
    __shared__ float Bs[BKt][BNt];
    int tid = threadIdx.x;
    int bm = blockIdx.y * BMt, bn = blockIdx.x * BNt;
    int ar = tid >> 2, ak = (tid & 3) << 2;
    int ty = tid >> 4, tx = tid & 15;
    float acc[4][4] = {};
    for (int k0 = 0; k0 < K; k0 += BKt) {
        float4 av = *(const float4*)(A + (size_t)(bm + ar) * K + k0 + ak);
        float4 bv = *(const float4*)(B + (size_t)(bn + ar) * K + k0 + ak);
        As[ak + 0][ar] = av.x; As[ak + 1][ar] = av.y; As[ak + 2][ar] = av.z; As[ak + 3][ar] = av.w;
        Bs[ak + 0][ar] = bv.x; Bs[ak + 1][ar] = bv.y; Bs[ak + 2][ar] = bv.z; Bs[ak + 3][ar] = bv.w;
        __syncthreads();
#pragma unroll
        for (int kk = 0; kk < BKt; kk++) {
            float4 a = *(const float4*)&As[kk][ty << 2];
            float4 b = *(const float4*)&Bs[kk][tx << 2];
            float ar4[4] = {a.x, a.y, a.z, a.w};
            float br4[4] = {b.x, b.y, b.z, b.w};
#pragma unroll
            for (int i = 0; i < 4; i++)
#pragma unroll
                for (int j = 0; j < 4; j++)
                    acc[i][j] = fmaf(ar4[i], br4[j], acc[i][j]);
        }
        __syncthreads();
    }
#pragma unroll
    for (int i = 0; i < 4; i++) {
        float s = 0.0f;
#pragma unroll
        for (int j = 0; j < 4; j++) {
            int n = bn + (tx << 2) + j;
            s += tanhfast(acc[i][j] + ba[n]) * wv[n];
        }
        s += __shfl_down_sync(0xffffffffu, s, 8, 16);
        s += __shfl_down_sync(0xffffffffu, s, 4, 16);
        s += __shfl_down_sync(0xffffffffu, s, 2, 16);
        s += __shfl_down_sync(0xffffffffu, s, 1, 16);
        if (tx == 0) atomicAdd(&logits[bm + (ty << 2) + i], s);
    }
}

// ---------------- LSTM pointwise: gates -> (h,c), writes out_seq[t][w][dir*HH+j] ----------------
__global__ void lstm_pointwise(float* __restrict__ out_seq, int s, int T) {
    int idx = blockIdx.x * blockDim.x + threadIdx.x;
    if (idx >= 2 * NW * HH) return;
    int j = idx % HH; int rest = idx / HH; int w = rest % NW; int dir = rest / NW;
    const float* g = g_gates + ((size_t)dir * NW + w) * G;
    float gi = sigf(g[j]);
    float gf = sigf(g[HH + j]);
    float gg = tanhfast(g[2 * HH + j]);
    float go = sigf(g[3 * HH + j]);
    float c = gf * g_c[idx] + gi * gg;
    float h = go * tanhfast(c);
    g_c[idx] = c; g_h[idx] = h;
    int t = dir ? (T - 1 - s) : s;
    out_seq[((size_t)t * NW + w) * Hd + dir * HH + j] = h;
}

// ---------------- attention softmax over t + context accumulation ----------------
__global__ void attn_ctx(const float* __restrict__ logits, const float* __restrict__ out_seq,
                         int T, int off) {
    int w = blockIdx.x;
    int tid = threadIdx.x;   // 256 = H
    __shared__ float p[16];
    if (tid == 0) {
        float l[16];
        float mx = -1e30f;
        for (int t = 0; t < T; t++) { l[t] = logits[t * NW + w]; mx = fmaxf(mx, l[t]); }
        float s = 0.0f;
        for (int t = 0; t < T; t++) { float e = __expf(l[t] - mx); p[t] = e; s += e; }
        float inv = 1.0f / s;
        for (int t = 0; t < T; t++) p[t] *= inv;
    }
    __syncthreads();
    float acc = 0.0f;
    for (int t = 0; t < T; t++)
        acc += p[t] * out_seq[((size_t)t * NW + w) * Hd + tid];
    g_xword[(size_t)w * XW + off + tid] = acc;
}

// ---------------- single-SM-per-direction word BiLSTM, k-split f32x2, spill-proof ----------
// 2 CTAs (one per direction), 512 threads = 128 j x 4 k-quarters.
// Weight split per gate-slot: 20 k in registers (10 packed f32x2), 12 k in smem (3x16B).
// -> 40 u64 weight regs (80 regs), ~105 live total: safely under the 128-reg RF cap.
// Direction-specialized inner loop (immediates for strides), 32-bit gin/out offsets.
#define HQ 36                     // padded quarter stride (floats)
#define HBUF (4 * HQ)             // one h buffer (144 floats)
#define WSLOTS 12                 // 4 gate-slots x 3 chunks
#define WLS_SMEM (WSLOTS * 512 * 16 + 2 * HBUF * 4 + 64)

template<int TSTEP>
__device__ __forceinline__ void wl_loop(
    const unsigned long long* wreg, uint32_t wsm_a, float* hsm,
    const float* gbase, float* obase, int t0, int kq) {
    int goff = t0 * G;
    int ooff = t0 * Hd;
    float ginv = __ldg(gbase + goff);
    float creg = 0.0f;
    for (int s = 0; s < NW; s++) {
        const float* hs = hsm + (s & 1) * HBUF + kq * HQ;
        float gnext = 0.0f;
        if (s + 1 < NW) gnext = __ldg(gbase + goff + TSTEP * G);
        goff += TSTEP * G;

        unsigned long long a0, a1, a2, a3;
        {
            ulonglong2 hv = *(const ulonglong2*)(hs);
            asm("mul.rn.f32x2 %0, %1, %2;" : "=l"(a0) : "l"(wreg[0]),  "l"(hv.x));
            asm("mul.rn.f32x2 %0, %1, %2;" : "=l"(a1) : "l"(wreg[10]), "l"(hv.x));
            asm("mul.rn.f32x2 %0, %1, %2;" : "=l"(a2) : "l"(wreg[20]), "l"(hv.x));
            asm("mul.rn.f32x2 %0, %1, %2;" : "=l"(a3) : "l"(wreg[30]), "l"(hv.x));
            fma2(a0, wreg[1],  hv.y);
            fma2(a1, wreg[11], hv.y);
            fma2(a2, wreg[21], hv.y);
            fma2(a3, wreg[31], hv.y);
        }
#pragma unroll
        for (int ch = 1; ch < 5; ch++) {        // k in [4ch, 4ch+4), register half (k<20)
            ulonglong2 hv = *(const ulonglong2*)(hs + 4 * ch);
            fma2(a0, wreg[2 * ch],      hv.x); fma2(a0, wreg[2 * ch + 1],      hv.y);
            fma2(a1, wreg[10 + 2 * ch], hv.x); fma2(a1, wreg[10 + 2 * ch + 1], hv.y);
            fma2(a2, wreg[20 + 2 * ch], hv.x); fma2(a2, wreg[20 + 2 * ch + 1], hv.y);
            fma2(a3, wreg[30 + 2 * ch], hv.x); fma2(a3, wreg[30 + 2 * ch + 1], hv.y);
        }
#pragma unroll
        for (int c = 0; c < 3; c++) {           // k in [20+4c, 24+4c), smem half
            ulonglong2 hv = *(const ulonglong2*)(hs + 20 + 4 * c);
            unsigned long long w0, w1;
            asm volatile("ld.shared.v2.u64 {%0,%1}, [%2];" : "=l"(w0), "=l"(w1)
                         : "r"(wsm_a + (uint32_t)((0 * 3 + c) * 512 * 16)));
            fma2(a0, w0, hv.x); fma2(a0, w1, hv.y);
            asm volatile("ld.shared.v2.u64 {%0,%1}, [%2];" : "=l"(w0), "=l"(w1)
                         : "r"(wsm_a + (uint32_t)((1 * 3 + c) * 512 * 16)));
            fma2(a1, w0, hv.x); fma2(a1, w1, hv.y);
            asm volatile("ld.shared.v2.u64 {%0,%1}, [%2];" : "=l"(w0), "=l"(w1)
                         : "r"(wsm_a + (uint32_t)((2 * 3 + c) * 512 * 16)));
            fma2(a2, w0, hv.x); fma2(a2, w1, hv.y);
            asm volatile("ld.shared.v2.u64 {%0,%1}, [%2];" : "=l"(w0), "=l"(w1)
                         : "r"(wsm_a + (uint32_t)((3 * 3 + c) * 512 * 16)));
            fma2(a3, w0, hv.x); fma2(a3, w1, hv.y);
        }
        float p0 = upsum(a0), p1 = upsum(a1), p2 = upsum(a2), p3 = upsum(a3);
        // 3-shfl butterfly: each lane ends with the full sum of ITS gate (slot-rotated)
        float s0 = p0 + __shfl_xor_sync(0xffffffffu, p1, 1, 4);
        float s2 = p2 + __shfl_xor_sync(0xffffffffu, p3, 1, 4);
        float tot = s0 + __shfl_xor_sync(0xffffffffu, s2, 2, 4) + ginv;
        ginv = gnext;
        float act = (kq == 2) ? tanhfast(tot) : sigf(tot);
        float af = __shfl_sync(0xffffffffu, act, 1, 4);
        float ag = __shfl_sync(0xffffffffu, act, 2, 4);
        float ao = __shfl_sync(0xffffffffu, act, 3, 4);
        if (kq == 0) {
            creg = af * creg + act * ag;
            float hh = ao * tanhfast(creg);
            int j = (int)(threadIdx.x >> 2);
            float* hw = hsm + ((s + 1) & 1) * HBUF;
            hw[(j >> 5) * HQ + (j & 31)] = hh;
            obase[ooff] = hh;
        }
        ooff += TSTEP * Hd;
        __syncthreads();
    }
}

__global__ void __launch_bounds__(512, 1) word_lstm_v5(const float* __restrict__ Whh) {
    extern __shared__ __align__(16) unsigned char sm_raw[];
    ulonglong2* wsm = (ulonglong2*)sm_raw;                   // [WSLOTS][512]
    float* hsm = (float*)(sm_raw + WSLOTS * 512 * 16);       // [2][HBUF]

    int dir = blockIdx.x;
    int tid = threadIdx.x;
    int j  = tid >> 2;
    int kq = tid & 3;

    const float* Wd = Whh + (size_t)dir * (G * HH);
    // slot i corresponds to gate g = kq ^ i
    unsigned long long wreg[40];
#pragma unroll
    for (int i = 0; i < 4; i++) {
        int g = kq ^ i;
        const float* Wr = Wd + (size_t)(g * HH + j) * HH + kq * 32;
#pragma unroll
        for (int m = 0; m < 10; m++)
            wreg[i * 10 + m] = *(const unsigned long long*)(Wr + 2 * m);
#pragma unroll
        for (int c = 0; c < 3; c++)
            wsm[(i * 3 + c) * 512 + tid] = *(const ulonglong2*)(Wr + 20 + 4 * c);
    }
    if (tid < 2 * HBUF) hsm[tid] = 0.0f;
    __syncthreads();

    uint32_t wsm_a = smem_u32(wsm) + (uint32_t)tid * 16u;
    const float* gbase = g_gin_word + (size_t)dir * NW * G + kq * HH + j;
    float* obase = g_outword + dir * HH + j;
    if (dir == 0) wl_loop<1>(wreg, wsm_a, hsm, gbase, obase, 0, kq);
    else          wl_loop<-1>(wreg, wsm_a, hsm, gbase, obase, NW - 1, kq);
}

// ---------------- final linear + log_softmax ----------------
__global__ void tag_kernel(const float* __restrict__ Wp, const float* __restrict__ bp,
                           const float* __restrict__ Wn, const float* __restrict__ bn,
                           float* __restrict__ out) {
    int w = blockIdx.x;
    int tid = threadIdx.x;  // 64
    __shared__ float o[Hd];
    __shared__ float sc[64];
    __shared__ float sc2[16];
    __shared__ float zp, zn;
    for (int d = tid; d < Hd; d += 64) o[d] = g_outword[(size_t)w * Hd + d];
    __syncthreads();
    if (tid < NPOS) {
        float s = bp[tid];
        for (int k = 0; k < Hd; k++) s = fmaf(o[k], Wp[tid * Hd + k], s);
        sc[tid] = s;
    }
    if (tid < NNER) {
        float s = bn[tid];
        for (int k = 0; k < Hd; k++) s = fmaf(o[k], Wn[tid * Hd + k], s);
        sc2[tid] = s;
    }
    __syncthreads();
    if (tid == 0) {
        float m = -1e30f;
        for (int i = 0; i < NPOS; i++) m = fmaxf(m, sc[i]);
        float s = 0.0f;
        for (int i = 0; i < NPOS; i++) s += __expf(sc[i] - m);
        zp = m + logf(s);
    }
    if (tid == 1) {
        float m = -1e30f;
        for (int i = 0; i < NNER; i++) m = fmaxf(m, sc2[i]);
        float s = 0.0f;
        for (int i = 0; i < NNER; i++) s += __expf(sc2[i] - m);
        zn = m + logf(s);
    }
    __syncthreads();
    if (tid < NPOS) out[(size_t)w * NPOS + tid] = sc[tid] - zp;
    if (tid < NNER) out[(size_t)NW * NPOS + (size_t)w * NNER + tid] = sc2[tid] - zn;
}

// ---------------- host launch ----------------
extern "C" void kernel_launch(void* const* d_in, const int* in_sizes, int n_in,
                              void* d_out, int out_size) {
    const int* word_seq = (const int*)d_in[0];
    const int* syl_seq  = (const int*)d_in[1];
    const int* char_seq = (const int*)d_in[2];
    const int* feat_seq = (const int*)d_in[3];
    const float* emb_char   = (const float*)d_in[4];
    const float* emb_syl    = (const float*)d_in[5];
    const float* emb_word   = (const float*)d_in[6];
    const float* emb_prefix = (const float*)d_in[7];
    const float* attn_c_W = (const float*)d_in[8];
    const float* attn_c_b = (const float*)d_in[9];
    const float* attn_c_w = (const float*)d_in[10];
    const float* attn_s_W = (const float*)d_in[11];
    const float* attn_s_b = (const float*)d_in[12];
    const float* attn_s_w = (const float*)d_in[13];
    const float* Wih_c = (const float*)d_in[14];
    const float* Whh_c = (const float*)d_in[15];
    const float* bih_c = (const float*)d_in[16];
    const float* bhh_c = (const float*)d_in[17];
    const float* Wih_s = (const float*)d_in[18];
    const float* Whh_s = (const float*)d_in[19];
    const float* bih_s = (const float*)d_in[20];
    const float* bhh_s = (const float*)d_in[21];
    const float* Wih_w = (const float*)d_in[22];
    const float* Whh_w = (const float*)d_in[23];
    const float* bih_w = (const float*)d_in[24];
    const float* bhh_w = (const float*)d_in[25];
    const float* W_pos = (const float*)d_in[26];
    const float* b_pos = (const float*)d_in[27];
    const float* W_ner = (const float*)d_in[28];
    const float* b_ner = (const float*)d_in[29];
    float* out = (float*)d_out;

    cudaFuncSetAttribute(word_lstm_v5, cudaFuncAttributeMaxDynamicSharedMemorySize, WLS_SMEM);

    float *p_x_char, *p_x_syl, *p_gin_char, *p_gin_syl, *p_gin_word;
    float *p_out_char, *p_out_syl, *p_h, *p_gates, *p_lg_char, *p_lg_syl, *p_xword;
    cudaGetSymbolAddress((void**)&p_x_char, g_x_char);
    cudaGetSymbolAddress((void**)&p_x_syl, g_x_syl);
    cudaGetSymbolAddress((void**)&p_gin_char, g_gin_char);
    cudaGetSymbolAddress((void**)&p_gin_syl, g_gin_syl);
    cudaGetSymbolAddress((void**)&p_gin_word, g_gin_word);
    cudaGetSymbolAddress((void**)&p_out_char, g_out_char);
    cudaGetSymbolAddress((void**)&p_out_syl, g_out_syl);
    cudaGetSymbolAddress((void**)&p_h, g_h);
    cudaGetSymbolAddress((void**)&p_gates, g_gates);
    cudaGetSymbolAddress((void**)&p_lg_char, g_logits_char);
    cudaGetSymbolAddress((void**)&p_lg_syl, g_logits_syl);
    cudaGetSymbolAddress((void**)&p_xword, g_xword);

    // 0) clear attention logits
    clear_logits_kernel<<<(TC * NW + 255) / 256, 256>>>();
    // 1) embedding gathers + h0/c0 init
    {
        int total = NW * TC * CD + NW * TS * SD + 2 * NW * HH + NW * WD;
        gather_kernel<<<(total + 255) / 256, 256>>>(word_seq, syl_seq, char_seq, feat_seq,
                                                    emb_char, emb_syl, emb_word, emb_prefix);
    }
    // 2) input projections (Gin = x @ Wih^T + bih + bhh) for char & syl, both dirs
    gemm64<<<dim3(G / 64, (NW * TC) / 64, 2), 256>>>(
        p_x_char, 0, Wih_c, (long long)G * CD,
        nullptr, 0, 0, bih_c, bhh_c, G,
        p_gin_char, (long long)NW * TC * G, NW * TC, G, CD);
    gemm64<<<dim3(G / 64, (NW * TS) / 64, 2), 256>>>(
        p_x_syl, 0, Wih_s, (long long)G * SD,
        nullptr, 0, 0, bih_s, bhh_s, G,
        p_gin_syl, (long long)NW * TS * G, NW * TS, G, SD);

    // 3) char BiLSTM recurrence (12 steps, both dirs per launch)
    for (int s = 0; s < TC; s++) {
        gemm64<<<dim3(G / 64, NW / 64, 2), 256>>>(
            p_h, (long long)NW * HH, Whh_c, (long long)G * HH,
            p_gin_char + (size_t)s * G,
            (long long)NW * TC * G + (long long)(TC - 1 - 2 * s) * G, TC * G,
            nullptr, nullptr, 0,
            p_gates, (long long)NW * G, NW, G, HH);
        lstm_pointwise<<<(2 * NW * HH + 255) / 256, 256>>>(p_out_char, s, TC);
    }
    // 4) char attention -> char_ctx into xword[:,256:512]
    gemm_attn<<<dim3(Hd / 64, (TC * NW) / 64), 256>>>(p_out_char, attn_c_W, attn_c_b, attn_c_w,
                                                      p_lg_char, TC * NW, Hd);
    attn_ctx<<<NW, Hd>>>(p_lg_char, p_out_char, TC, WD);

    // 5) syl BiLSTM (reinit state from h0, c=0)
    reinit_state_kernel<<<(2 * NW * HH + 255) / 256, 256>>>();
    for (int s = 0; s < TS; s++) {
        gemm64<<<dim3(G / 64, NW / 64, 2), 256>>>(
            p_h, (long long)NW * HH, Whh_s, (long long)G * HH,
            p_gin_syl + (size_t)s * G,
            (long long)NW * TS * G + (long long)(TS - 1 - 2 * s) * G, TS * G,
            nullptr, nullptr, 0,
            p_gates, (long long)NW * G, NW, G, HH);
        lstm_pointwise<<<(2 * NW * HH + 255) / 256, 256>>>(p_out_syl, s, TS);
    }
    // 6) syl attention -> syl_ctx into xword[:,512:768]
    gemm_attn<<<dim3(Hd / 64, (TS * NW) / 64), 256>>>(p_out_syl, attn_s_W, attn_s_b, attn_s_w,
                                                      p_lg_syl, TS * NW, Hd);
    attn_ctx<<<NW, Hd>>>(p_lg_syl, p_out_syl, TS, WD + Hd);

    // 7) word-level input projection
    gemm64<<<dim3(G / 64, NW / 64, 2), 256>>>(
        p_xword, 0, Wih_w, (long long)G * XW,
        nullptr, 0, 0, bih_w, bhh_w, G,
        p_gin_word, (long long)NW * G, NW, G, XW);

    // 8) sequential word BiLSTM (1 CTA per direction, k-split f32x2, spill-proof)
    word_lstm_v5<<<2, 512, WLS_SMEM>>>(Whh_w);

    // 9) final linear + log_softmax -> [pos(2048x47) | ner(2048x13)]
    tag_kernel<<<NW, 64>>>(W_pos, b_pos, W_ner, b_ner, out);
}